// round 14
// baseline (speedup 1.0000x reference)
#include <cuda_runtime.h>

#define J3 768
#define NC 256

__device__ __align__(16) uint4 g_wqkvP[24576];   // [jj 0..47][kt 0..15][lane] fp16 A-frags
__device__ __align__(16) uint4 g_wprojP[8192];   // [cc 0..15][kt 0..15][lane]
__device__ __align__(16) unsigned short g_qkv[(size_t)1024 * 128 * J3];
__device__ __align__(16) unsigned short g_o[(size_t)1024 * 128 * NC];

__device__ __forceinline__ unsigned pack2(float lo, float hi) {
    unsigned u; asm("cvt.rn.f16x2.f32 %0, %1, %2;" : "=r"(u) : "f"(hi), "f"(lo)); return u;
}
__device__ __forceinline__ float ex2(float x) {
    float y; asm("ex2.approx.f32 %0, %1;" : "=f"(y) : "f"(x)); return y;
}
__device__ __forceinline__ unsigned sptr(const void* p) {
    return (unsigned)__cvta_generic_to_shared(p);
}
__device__ __forceinline__ void cp16(unsigned dst, const void* src) {
    asm volatile("cp.async.ca.shared.global [%0], [%1], 16;\n" :: "r"(dst), "l"(src));
}
__device__ __forceinline__ void cp_commit() { asm volatile("cp.async.commit_group;\n"); }
template<int N> __device__ __forceinline__ void cp_wait() {
    asm volatile("cp.async.wait_group %0;\n" :: "n"(N));
}
__device__ __forceinline__ void ldsm4(unsigned* r, unsigned addr) {
    asm volatile("ldmatrix.sync.aligned.m8n8.x4.shared.b16 {%0,%1,%2,%3}, [%4];"
        : "=r"(r[0]), "=r"(r[1]), "=r"(r[2]), "=r"(r[3]) : "r"(addr));
}
__device__ __forceinline__ void ldsm4t(unsigned* r, unsigned addr) {
    asm volatile("ldmatrix.sync.aligned.m8n8.x4.trans.shared.b16 {%0,%1,%2,%3}, [%4];"
        : "=r"(r[0]), "=r"(r[1]), "=r"(r[2]), "=r"(r[3]) : "r"(addr));
}
// m16n8k16 fp16: A row-major a0=(g,2q,2q+1) a1=(g+8,..) a2=(g,2q+8..) a3=(g+8,2q+8..)
// B col-major b0=(k 2q,2q+1; n g) b1=(k 2q+8..; n g); C c0=(g,2q) c1=(g,2q+1) c2/c3 +8 rows
__device__ __forceinline__ void mma16(float* c, const unsigned* a, unsigned b0, unsigned b1) {
    asm volatile(
        "mma.sync.aligned.m16n8k16.row.col.f32.f16.f16.f32 "
        "{%0,%1,%2,%3},{%4,%5,%6,%7},{%8,%9},{%0,%1,%2,%3};\n"
        : "+f"(c[0]), "+f"(c[1]), "+f"(c[2]), "+f"(c[3])
        : "r"(a[0]), "r"(a[1]), "r"(a[2]), "r"(a[3]), "r"(b0), "r"(b1));
}

// Prepack weights as fp16 m16n8k16 A-fragments (one LDG.128 per warp per frag).
__global__ void k_prep(const float* __restrict__ Wqkv, const float* __restrict__ Wproj) {
    int i = blockIdx.x * 256 + threadIdx.x;       // 0..32767
    int lane = i & 31, g = lane >> 2, q = lane & 3;
    if (i < 24576) {
        int e = i >> 5, kt = e & 15, jj = e >> 4;
        int j = jj * 16 + g, c0 = kt * 16;
        uint4 u;
        u.x = pack2(Wqkv[(c0 + 2*q)     * J3 + j],     Wqkv[(c0 + 2*q + 1) * J3 + j]);
        u.y = pack2(Wqkv[(c0 + 2*q)     * J3 + j + 8], Wqkv[(c0 + 2*q + 1) * J3 + j + 8]);
        u.z = pack2(Wqkv[(c0 + 2*q + 8) * J3 + j],     Wqkv[(c0 + 2*q + 9) * J3 + j]);
        u.w = pack2(Wqkv[(c0 + 2*q + 8) * J3 + j + 8], Wqkv[(c0 + 2*q + 9) * J3 + j + 8]);
        g_wqkvP[i] = u;
    } else {
        int ii = i - 24576;                        // 0..8191
        int e = ii >> 5, kt = e & 15, cc = e >> 4;
        int c = cc * 16 + g, k0 = kt * 16;
        uint4 u;
        u.x = pack2(Wproj[(k0 + 2*q)     * NC + c],     Wproj[(k0 + 2*q + 1) * NC + c]);
        u.y = pack2(Wproj[(k0 + 2*q)     * NC + c + 8], Wproj[(k0 + 2*q + 1) * NC + c + 8]);
        u.z = pack2(Wproj[(k0 + 2*q + 8) * NC + c],     Wproj[(k0 + 2*q + 9) * NC + c]);
        u.w = pack2(Wproj[(k0 + 2*q + 8) * NC + c + 8], Wproj[(k0 + 2*q + 9) * NC + c + 8]);
        g_wprojP[ii] = u;
    }
}

// ---------- QKV projection: per (t,b,wh) CTA: D[j 768][w 64] fp16, 2 CTAs/SM
// Warp = 64 j x 32 w (4 mt x 4 nt): B-ldsm dup 4x (was 8x).
__global__ void __launch_bounds__(256, 2) k_qkv(const float* __restrict__ x,
                                                const float* __restrict__ bqkv) {
    extern __shared__ unsigned shm[];
    unsigned short* Xs = (unsigned short*)shm;    // [256 c][72] halves
    float* Ds = (float*)(shm + (256 * 72) / 2);   // [64 w][132] floats
    const int t = blockIdx.x, b = blockIdx.y, wh = blockIdx.z;
    const int tid = threadIdx.x, lane = tid & 31, wid = tid >> 5;
    const int g = lane >> 2, q = lane & 3;
    const int wmj = wid & 3, wnw = wid >> 2;      // 4 j-tiles x 2 w-halves

    const int bro = (lane & 7) + (((lane >> 3) & 1) << 3);
    const int bco = (lane >> 4) << 3;

    const float* xb = x + ((size_t)b * NC * 128 + t) * 128 + wh * 64;
    #pragma unroll
    for (int p = 0; p < 16; p++) {
        int l = tid + p * 256;
        int c = l >> 4, colw = (l & 15) * 4;
        float4 v = *(const float4*)(xb + (size_t)c * 16384 + colw);
        uint2 u = { pack2(v.x, v.y), pack2(v.z, v.w) };
        *(uint2*)(Xs + c * 72 + colw) = u;
    }
    __syncthreads();

    for (int jb = 0; jb < 3; jb++) {
        float acc[4][4][4];
        #pragma unroll
        for (int mt = 0; mt < 4; mt++)
            #pragma unroll
            for (int nt = 0; nt < 4; nt++)
                #pragma unroll
                for (int i = 0; i < 4; i++) acc[mt][nt][i] = 0.f;

        const int jj0 = jb * 16 + wmj * 4;
        #pragma unroll 2
        for (int kt = 0; kt < 16; kt++) {
            uint4 af[4];
            #pragma unroll
            for (int mt = 0; mt < 4; mt++)
                af[mt] = g_wqkvP[((jj0 + mt) * 16 + kt) * 32 + lane];
            #pragma unroll
            for (int p = 0; p < 2; p++) {
                unsigned bb[4];
                ldsm4t(bb, sptr(Xs + (kt * 16 + bro) * 72 + wnw * 32 + p * 16 + bco));
                #pragma unroll
                for (int mt = 0; mt < 4; mt++) {
                    mma16(acc[mt][p * 2],     (const unsigned*)&af[mt], bb[0], bb[1]);
                    mma16(acc[mt][p * 2 + 1], (const unsigned*)&af[mt], bb[2], bb[3]);
                }
            }
        }

        float bl[4][2];
        #pragma unroll
        for (int mt = 0; mt < 4; mt++) {
            bl[mt][0] = bqkv[jb * 256 + wmj * 64 + mt * 16 + g];
            bl[mt][1] = bqkv[jb * 256 + wmj * 64 + mt * 16 + g + 8];
        }

        #pragma unroll
        for (int half = 0; half < 2; half++) {
            __syncthreads();
            if ((wmj >> 1) == half) {
                #pragma unroll
                for (int mt = 0; mt < 4; mt++)
                    #pragma unroll
                    for (int nt = 0; nt < 4; nt++) {
                        int w0 = wnw * 32 + nt * 8 + 2 * q;
                        int jl = (wmj & 1) * 64 + mt * 16 + g;
                        Ds[w0 * 132 + jl]           = acc[mt][nt][0] + bl[mt][0];
                        Ds[(w0 + 1) * 132 + jl]     = acc[mt][nt][1] + bl[mt][0];
                        Ds[w0 * 132 + jl + 8]       = acc[mt][nt][2] + bl[mt][1];
                        Ds[(w0 + 1) * 132 + jl + 8] = acc[mt][nt][3] + bl[mt][1];
                    }
            }
            __syncthreads();
            #pragma unroll
            for (int p = 0; p < 8; p++) {
                int l = tid + p * 256;
                int w = l >> 5, col = (l & 31) * 4;
                float4 v = *(const float4*)(Ds + w * 132 + col);
                uint2 u = { pack2(v.x, v.y), pack2(v.z, v.w) };
                *(uint2*)(g_qkv + ((size_t)((b * 128 + wh * 64 + w) * 128 + t)) * J3
                          + jb * 256 + half * 128 + col) = u;
            }
        }
    }
}

// ---------- attention per (head, s), fp16, 2 CTAs/SM; P stays in registers
__global__ void __launch_bounds__(256, 2) k_attn() {
    extern __shared__ unsigned shm[];
    unsigned short* Qs = (unsigned short*)shm;     // [128][72]
    unsigned short* Ks = Qs + 128 * 72;            // [128][72]
    unsigned short* Vs = Qs + 2 * 128 * 72;        // [128][72]
    const int head = blockIdx.x, s = blockIdx.y;
    const int tid = threadIdx.x, lane = tid & 31, wid = tid >> 5;
    const int g = lane >> 2, q = lane & 3;
    const int m0 = wid * 16;
    const int arow = lane & 15, aco = (lane >> 4) << 3;
    const int kro = (lane & 7) + ((lane >> 4) << 3);
    const int kco = (((lane >> 3) & 1) << 3);
    const int vro = (lane & 7) + (((lane >> 3) & 1) << 3);
    const int vco = (lane >> 4) << 3;

    const unsigned short* base = g_qkv + (size_t)s * 128 * J3 + head * 64;
    const int r0 = tid >> 3, sg = tid & 7;
    #pragma unroll
    for (int p = 0; p < 4; p++) {                  // group 0: Q + K
        int tt = r0 + p * 32;
        const unsigned short* row = base + (size_t)tt * J3;
        cp16(sptr(Qs + tt * 72 + sg * 8), row + sg * 8);
        cp16(sptr(Ks + tt * 72 + sg * 8), row + 256 + sg * 8);
    }
    cp_commit();
    #pragma unroll
    for (int p = 0; p < 4; p++) {                  // group 1: V
        int tt = r0 + p * 32;
        cp16(sptr(Vs + tt * 72 + sg * 8), base + (size_t)tt * J3 + 512 + sg * 8);
    }
    cp_commit();
    cp_wait<1>();
    __syncthreads();

    float sa[16][4];
    #pragma unroll
    for (int nt = 0; nt < 16; nt++)
        #pragma unroll
        for (int i = 0; i < 4; i++) sa[nt][i] = 0.f;

    #pragma unroll
    for (int kt = 0; kt < 4; kt++) {
        unsigned a[4];
        ldsm4(a, sptr(Qs + (m0 + arow) * 72 + kt * 16 + aco));
        #pragma unroll
        for (int p = 0; p < 8; p++) {
            unsigned bb[4];
            ldsm4(bb, sptr(Ks + (p * 16 + kro) * 72 + kt * 16 + kco));
            mma16(sa[p * 2],     a, bb[0], bb[1]);
            mma16(sa[p * 2 + 1], a, bb[2], bb[3]);
        }
    }

    // softmax: rows g (sa[][0,1]) and g+8 (sa[][2,3]); reduce across quad (q)
    const float k2e = 0.125f * 1.4426950408889634f;
    float mx0 = -1e30f, mx1 = -1e30f;
    #pragma unroll
    for (int nt = 0; nt < 16; nt++) {
        mx0 = fmaxf(mx0, fmaxf(sa[nt][0], sa[nt][1]));
        mx1 = fmaxf(mx1, fmaxf(sa[nt][2], sa[nt][3]));
    }
    mx0 = fmaxf(mx0, __shfl_xor_sync(0xffffffffu, mx0, 1));
    mx0 = fmaxf(mx0, __shfl_xor_sync(0xffffffffu, mx0, 2));
    mx1 = fmaxf(mx1, __shfl_xor_sync(0xffffffffu, mx1, 1));
    mx1 = fmaxf(mx1, __shfl_xor_sync(0xffffffffu, mx1, 2));
    float s0 = 0.f, s1 = 0.f;
    #pragma unroll
    for (int nt = 0; nt < 16; nt++) {
        sa[nt][0] = ex2((sa[nt][0] - mx0) * k2e);
        sa[nt][1] = ex2((sa[nt][1] - mx0) * k2e);
        sa[nt][2] = ex2((sa[nt][2] - mx1) * k2e);
        sa[nt][3] = ex2((sa[nt][3] - mx1) * k2e);
        s0 += sa[nt][0] + sa[nt][1];
        s1 += sa[nt][2] + sa[nt][3];
    }
    s0 += __shfl_xor_sync(0xffffffffu, s0, 1);
    s0 += __shfl_xor_sync(0xffffffffu, s0, 2);
    s1 += __shfl_xor_sync(0xffffffffu, s1, 1);
    s1 += __shfl_xor_sync(0xffffffffu, s1, 2);
    const float r0v = 1.f / s0, r1v = 1.f / s1;

    cp_wait<0>();                      // V ready
    __syncthreads();                   // V visible to all warps

    float oa[8][4];
    #pragma unroll
    for (int nt = 0; nt < 8; nt++)
        #pragma unroll
        for (int i = 0; i < 4; i++) oa[nt][i] = 0.f;

    // PV: S's C-fragment IS the A-fragment layout — P never touches smem.
    #pragma unroll
    for (int kt = 0; kt < 8; kt++) {
        unsigned a[4];
        a[0] = pack2(sa[2 * kt][0] * r0v,     sa[2 * kt][1] * r0v);
        a[1] = pack2(sa[2 * kt][2] * r1v,     sa[2 * kt][3] * r1v);
        a[2] = pack2(sa[2 * kt + 1][0] * r0v, sa[2 * kt + 1][1] * r0v);
        a[3] = pack2(sa[2 * kt + 1][2] * r1v, sa[2 * kt + 1][3] * r1v);
        #pragma unroll
        for (int p = 0; p < 4; p++) {
            unsigned bb[4];
            ldsm4t(bb, sptr(Vs + (kt * 16 + vro) * 72 + p * 16 + vco));
            mma16(oa[p * 2],     a, bb[0], bb[1]);
            mma16(oa[p * 2 + 1], a, bb[2], bb[3]);
        }
    }

    unsigned short* ob = g_o + (size_t)s * 128 * NC + head * 64;
    #pragma unroll
    for (int nt = 0; nt < 8; nt++) {
        int d0 = nt * 8 + 2 * q;
        *(unsigned*)(ob + (size_t)(m0 + g) * NC + d0)     = pack2(oa[nt][0], oa[nt][1]);
        *(unsigned*)(ob + (size_t)(m0 + g + 8) * NC + d0) = pack2(oa[nt][2], oa[nt][3]);
    }
}

// ---------- output projection: per (t,b,wh) CTA over 64 w, 2 CTAs/SM
// Warp = 64 c x 32 w (4 mt x 4 nt): B-ldsm dup 4x (was 8x).
__global__ void __launch_bounds__(256, 2) k_proj(const float* __restrict__ bproj,
                                                 float* __restrict__ out) {
    extern __shared__ unsigned shm[];
    unsigned short* Os = (unsigned short*)shm;    // [64 w][264] halves
    const int t = blockIdx.x, b = blockIdx.y, wh = blockIdx.z;
    const int tid = threadIdx.x, lane = tid & 31, wid = tid >> 5;
    const int g = lane >> 2, q = lane & 3;
    const int wmc = wid & 3, wnw = wid >> 2;      // 4 c-tiles x 2 w-halves
    const int kro = (lane & 7) + ((lane >> 4) << 3);
    const int kco = (((lane >> 3) & 1) << 3);

    #pragma unroll
    for (int p = 0; p < 8; p++) {
        int l = tid + p * 256;
        int w = l >> 5, seg = l & 31;
        cp16(sptr(Os + w * 264 + seg * 8),
             g_o + ((size_t)((b * 128 + wh * 64 + w) * 128 + t)) * NC + seg * 8);
    }
    cp_commit();

    float acc[4][4][4];
    #pragma unroll
    for (int mt = 0; mt < 4; mt++)
        #pragma unroll
        for (int nt = 0; nt < 4; nt++)
            #pragma unroll
            for (int i = 0; i < 4; i++) acc[mt][nt][i] = 0.f;

    cp_wait<0>();
    __syncthreads();

    #pragma unroll 2
    for (int kt = 0; kt < 16; kt++) {
        uint4 af[4];
        #pragma unroll
        for (int mt = 0; mt < 4; mt++)
            af[mt] = g_wprojP[((wmc * 4 + mt) * 16 + kt) * 32 + lane];
        #pragma unroll
        for (int p = 0; p < 2; p++) {
            unsigned bb[4];
            ldsm4(bb, sptr(Os + (wnw * 32 + p * 16 + kro) * 264 + kt * 16 + kco));
            #pragma unroll
            for (int mt = 0; mt < 4; mt++) {
                mma16(acc[mt][p * 2],     (const unsigned*)&af[mt], bb[0], bb[1]);
                mma16(acc[mt][p * 2 + 1], (const unsigned*)&af[mt], bb[2], bb[3]);
            }
        }
    }

    #pragma unroll
    for (int mt = 0; mt < 4; mt++) {
        int c0 = wmc * 64 + mt * 16 + g;
        float bi0 = bproj[c0], bi1 = bproj[c0 + 8];
        #pragma unroll
        for (int nt = 0; nt < 4; nt++) {
            int w0 = wh * 64 + wnw * 32 + nt * 8 + 2 * q;
            float2 v0 = { acc[mt][nt][0] + bi0, acc[mt][nt][1] + bi0 };
            float2 v1 = { acc[mt][nt][2] + bi1, acc[mt][nt][3] + bi1 };
            *(float2*)(out + ((size_t)(b * NC + c0) * 128 + t) * 128 + w0) = v0;
            *(float2*)(out + ((size_t)(b * NC + c0 + 8) * 128 + t) * 128 + w0) = v1;
        }
    }
}

extern "C" void kernel_launch(void* const* d_in, const int* in_sizes, int n_in,
                              void* d_out, int out_size) {
    const float* x     = (const float*)d_in[0];
    const float* Wqkv  = (const float*)d_in[1];
    const float* bqkv  = (const float*)d_in[2];
    const float* Wproj = (const float*)d_in[3];
    const float* bproj = (const float*)d_in[4];
    float* out = (float*)d_out;

    cudaFuncSetAttribute(k_qkv,  cudaFuncAttributeMaxDynamicSharedMemorySize, 70656);
    cudaFuncSetAttribute(k_attn, cudaFuncAttributeMaxDynamicSharedMemorySize, 55296);
    cudaFuncSetAttribute(k_proj, cudaFuncAttributeMaxDynamicSharedMemorySize, 33792);

    k_prep<<<128, 256>>>(Wqkv, Wproj);
    k_qkv<<<dim3(128, 8, 2), 256, 70656>>>(x, bqkv);
    k_attn<<<dim3(4, 1024), 256, 55296>>>();
    k_proj<<<dim3(128, 8, 2), 256, 33792>>>(bproj, out);
}

// round 15
// speedup vs baseline: 1.0688x; 1.0688x over previous
#include <cuda_runtime.h>

#define J3 768
#define NC 256

__device__ __align__(16) uint4 g_wqkvP[24576];   // [jj 0..47][kt 0..15][lane] fp16 A-frags
__device__ __align__(16) uint4 g_wprojP[8192];   // [cc 0..15][kt 0..15][lane]
__device__ __align__(16) unsigned short g_qkv[(size_t)1024 * 128 * J3];
__device__ __align__(16) unsigned short g_o[(size_t)1024 * 128 * NC];

__device__ __forceinline__ unsigned pack2(float lo, float hi) {
    unsigned u; asm("cvt.rn.f16x2.f32 %0, %1, %2;" : "=r"(u) : "f"(hi), "f"(lo)); return u;
}
__device__ __forceinline__ float ex2(float x) {
    float y; asm("ex2.approx.f32 %0, %1;" : "=f"(y) : "f"(x)); return y;
}
__device__ __forceinline__ unsigned sptr(const void* p) {
    return (unsigned)__cvta_generic_to_shared(p);
}
__device__ __forceinline__ void cp16(unsigned dst, const void* src) {
    asm volatile("cp.async.ca.shared.global [%0], [%1], 16;\n" :: "r"(dst), "l"(src));
}
__device__ __forceinline__ void cp_commit() { asm volatile("cp.async.commit_group;\n"); }
template<int N> __device__ __forceinline__ void cp_wait() {
    asm volatile("cp.async.wait_group %0;\n" :: "n"(N));
}
__device__ __forceinline__ void ldsm4(unsigned* r, unsigned addr) {
    asm volatile("ldmatrix.sync.aligned.m8n8.x4.shared.b16 {%0,%1,%2,%3}, [%4];"
        : "=r"(r[0]), "=r"(r[1]), "=r"(r[2]), "=r"(r[3]) : "r"(addr));
}
__device__ __forceinline__ void ldsm4t(unsigned* r, unsigned addr) {
    asm volatile("ldmatrix.sync.aligned.m8n8.x4.trans.shared.b16 {%0,%1,%2,%3}, [%4];"
        : "=r"(r[0]), "=r"(r[1]), "=r"(r[2]), "=r"(r[3]) : "r"(addr));
}
// m16n8k16 fp16: A row-major a0=(g,2q,2q+1) a1=(g+8,..) a2=(g,2q+8..) a3=(g+8,2q+8..)
// B col-major b0=(k 2q,2q+1; n g) b1=(k 2q+8..; n g); C c0=(g,2q) c1=(g,2q+1) c2/c3 +8 rows
__device__ __forceinline__ void mma16(float* c, const unsigned* a, unsigned b0, unsigned b1) {
    asm volatile(
        "mma.sync.aligned.m16n8k16.row.col.f32.f16.f16.f32 "
        "{%0,%1,%2,%3},{%4,%5,%6,%7},{%8,%9},{%0,%1,%2,%3};\n"
        : "+f"(c[0]), "+f"(c[1]), "+f"(c[2]), "+f"(c[3])
        : "r"(a[0]), "r"(a[1]), "r"(a[2]), "r"(a[3]), "r"(b0), "r"(b1));
}

// Prepack weights as fp16 m16n8k16 A-fragments (one LDG.128 per warp per frag).
__global__ void k_prep(const float* __restrict__ Wqkv, const float* __restrict__ Wproj) {
    int i = blockIdx.x * 256 + threadIdx.x;       // 0..32767
    int lane = i & 31, g = lane >> 2, q = lane & 3;
    if (i < 24576) {
        int e = i >> 5, kt = e & 15, jj = e >> 4;
        int j = jj * 16 + g, c0 = kt * 16;
        uint4 u;
        u.x = pack2(Wqkv[(c0 + 2*q)     * J3 + j],     Wqkv[(c0 + 2*q + 1) * J3 + j]);
        u.y = pack2(Wqkv[(c0 + 2*q)     * J3 + j + 8], Wqkv[(c0 + 2*q + 1) * J3 + j + 8]);
        u.z = pack2(Wqkv[(c0 + 2*q + 8) * J3 + j],     Wqkv[(c0 + 2*q + 9) * J3 + j]);
        u.w = pack2(Wqkv[(c0 + 2*q + 8) * J3 + j + 8], Wqkv[(c0 + 2*q + 9) * J3 + j + 8]);
        g_wqkvP[i] = u;
    } else {
        int ii = i - 24576;                        // 0..8191
        int e = ii >> 5, kt = e & 15, cc = e >> 4;
        int c = cc * 16 + g, k0 = kt * 16;
        uint4 u;
        u.x = pack2(Wproj[(k0 + 2*q)     * NC + c],     Wproj[(k0 + 2*q + 1) * NC + c]);
        u.y = pack2(Wproj[(k0 + 2*q)     * NC + c + 8], Wproj[(k0 + 2*q + 1) * NC + c + 8]);
        u.z = pack2(Wproj[(k0 + 2*q + 8) * NC + c],     Wproj[(k0 + 2*q + 9) * NC + c]);
        u.w = pack2(Wproj[(k0 + 2*q + 8) * NC + c + 8], Wproj[(k0 + 2*q + 9) * NC + c + 8]);
        g_wprojP[ii] = u;
    }
}

// ---------- QKV projection (R12): per (t,b,wh) CTA: D[j 768][w 64] fp16, 2 CTAs/SM
// Warp = 32 j x 64 w (2 mt x 8 nt).
__global__ void __launch_bounds__(256, 2) k_qkv(const float* __restrict__ x,
                                                const float* __restrict__ bqkv) {
    extern __shared__ unsigned shm[];
    unsigned short* Xs = (unsigned short*)shm;    // [256 c][72] halves
    float* Ds = (float*)(shm + (256 * 72) / 2);   // [64 w][132] floats
    const int t = blockIdx.x, b = blockIdx.y, wh = blockIdx.z;
    const int tid = threadIdx.x, lane = tid & 31, wid = tid >> 5;
    const int g = lane >> 2, q = lane & 3;
    const int wm = wid;

    const int bro = (lane & 7) + (((lane >> 3) & 1) << 3);
    const int bco = (lane >> 4) << 3;

    const float* xb = x + ((size_t)b * NC * 128 + t) * 128 + wh * 64;
    #pragma unroll
    for (int p = 0; p < 16; p++) {
        int l = tid + p * 256;
        int c = l >> 4, colw = (l & 15) * 4;
        float4 v = *(const float4*)(xb + (size_t)c * 16384 + colw);
        uint2 u = { pack2(v.x, v.y), pack2(v.z, v.w) };
        *(uint2*)(Xs + c * 72 + colw) = u;
    }
    __syncthreads();

    for (int jb = 0; jb < 3; jb++) {
        float acc[2][8][4];
        #pragma unroll
        for (int mt = 0; mt < 2; mt++)
            #pragma unroll
            for (int nt = 0; nt < 8; nt++)
                #pragma unroll
                for (int i = 0; i < 4; i++) acc[mt][nt][i] = 0.f;

        const int jj0 = jb * 16 + wm * 2;
        #pragma unroll 4
        for (int kt = 0; kt < 16; kt++) {
            uint4 af0 = g_wqkvP[(jj0 * 16 + kt) * 32 + lane];
            uint4 af1 = g_wqkvP[((jj0 + 1) * 16 + kt) * 32 + lane];
            #pragma unroll
            for (int p = 0; p < 4; p++) {
                unsigned bb[4];
                ldsm4t(bb, sptr(Xs + (kt * 16 + bro) * 72 + p * 16 + bco));
                mma16(acc[0][p * 2],     (const unsigned*)&af0, bb[0], bb[1]);
                mma16(acc[0][p * 2 + 1], (const unsigned*)&af0, bb[2], bb[3]);
                mma16(acc[1][p * 2],     (const unsigned*)&af1, bb[0], bb[1]);
                mma16(acc[1][p * 2 + 1], (const unsigned*)&af1, bb[2], bb[3]);
            }
        }

        float bl[2][2];
        #pragma unroll
        for (int mt = 0; mt < 2; mt++) {
            bl[mt][0] = bqkv[jb * 256 + wm * 32 + mt * 16 + g];
            bl[mt][1] = bqkv[jb * 256 + wm * 32 + mt * 16 + g + 8];
        }

        #pragma unroll
        for (int half = 0; half < 2; half++) {
            __syncthreads();
            if ((wm >> 2) == half) {
                int jw = (wm & 3) * 32;
                #pragma unroll
                for (int mt = 0; mt < 2; mt++)
                    #pragma unroll
                    for (int nt = 0; nt < 8; nt++) {
                        int w0 = nt * 8 + 2 * q;
                        int jl = jw + mt * 16 + g;
                        Ds[w0 * 132 + jl]           = acc[mt][nt][0] + bl[mt][0];
                        Ds[(w0 + 1) * 132 + jl]     = acc[mt][nt][1] + bl[mt][0];
                        Ds[w0 * 132 + jl + 8]       = acc[mt][nt][2] + bl[mt][1];
                        Ds[(w0 + 1) * 132 + jl + 8] = acc[mt][nt][3] + bl[mt][1];
                    }
            }
            __syncthreads();
            #pragma unroll
            for (int p = 0; p < 8; p++) {
                int l = tid + p * 256;
                int w = l >> 5, col = (l & 31) * 4;
                float4 v = *(const float4*)(Ds + w * 132 + col);
                uint2 u = { pack2(v.x, v.y), pack2(v.z, v.w) };
                *(uint2*)(g_qkv + ((size_t)((b * 128 + wh * 64 + w) * 128 + t)) * J3
                          + jb * 256 + half * 128 + col) = u;
            }
        }
    }
}

// ---------- attention per (head, s), fp16, 2 CTAs/SM; P stays in registers
__global__ void __launch_bounds__(256, 2) k_attn() {
    extern __shared__ unsigned shm[];
    unsigned short* Qs = (unsigned short*)shm;     // [128][72]
    unsigned short* Ks = Qs + 128 * 72;            // [128][72]
    unsigned short* Vs = Qs + 2 * 128 * 72;        // [128][72]
    const int head = blockIdx.x, s = blockIdx.y;
    const int tid = threadIdx.x, lane = tid & 31, wid = tid >> 5;
    const int g = lane >> 2, q = lane & 3;
    const int m0 = wid * 16;
    const int arow = lane & 15, aco = (lane >> 4) << 3;
    const int kro = (lane & 7) + ((lane >> 4) << 3);
    const int kco = (((lane >> 3) & 1) << 3);
    const int vro = (lane & 7) + (((lane >> 3) & 1) << 3);
    const int vco = (lane >> 4) << 3;

    const unsigned short* base = g_qkv + (size_t)s * 128 * J3 + head * 64;
    const int r0 = tid >> 3, sg = tid & 7;
    #pragma unroll
    for (int p = 0; p < 4; p++) {                  // group 0: Q + K
        int tt = r0 + p * 32;
        const unsigned short* row = base + (size_t)tt * J3;
        cp16(sptr(Qs + tt * 72 + sg * 8), row + sg * 8);
        cp16(sptr(Ks + tt * 72 + sg * 8), row + 256 + sg * 8);
    }
    cp_commit();
    #pragma unroll
    for (int p = 0; p < 4; p++) {                  // group 1: V
        int tt = r0 + p * 32;
        cp16(sptr(Vs + tt * 72 + sg * 8), base + (size_t)tt * J3 + 512 + sg * 8);
    }
    cp_commit();
    cp_wait<1>();
    __syncthreads();

    float sa[16][4];
    #pragma unroll
    for (int nt = 0; nt < 16; nt++)
        #pragma unroll
        for (int i = 0; i < 4; i++) sa[nt][i] = 0.f;

    #pragma unroll
    for (int kt = 0; kt < 4; kt++) {
        unsigned a[4];
        ldsm4(a, sptr(Qs + (m0 + arow) * 72 + kt * 16 + aco));
        #pragma unroll
        for (int p = 0; p < 8; p++) {
            unsigned bb[4];
            ldsm4(bb, sptr(Ks + (p * 16 + kro) * 72 + kt * 16 + kco));
            mma16(sa[p * 2],     a, bb[0], bb[1]);
            mma16(sa[p * 2 + 1], a, bb[2], bb[3]);
        }
    }

    // softmax: rows g (sa[][0,1]) and g+8 (sa[][2,3]); reduce across quad (q)
    const float k2e = 0.125f * 1.4426950408889634f;
    float mx0 = -1e30f, mx1 = -1e30f;
    #pragma unroll
    for (int nt = 0; nt < 16; nt++) {
        mx0 = fmaxf(mx0, fmaxf(sa[nt][0], sa[nt][1]));
        mx1 = fmaxf(mx1, fmaxf(sa[nt][2], sa[nt][3]));
    }
    mx0 = fmaxf(mx0, __shfl_xor_sync(0xffffffffu, mx0, 1));
    mx0 = fmaxf(mx0, __shfl_xor_sync(0xffffffffu, mx0, 2));
    mx1 = fmaxf(mx1, __shfl_xor_sync(0xffffffffu, mx1, 1));
    mx1 = fmaxf(mx1, __shfl_xor_sync(0xffffffffu, mx1, 2));
    float s0 = 0.f, s1 = 0.f;
    #pragma unroll
    for (int nt = 0; nt < 16; nt++) {
        sa[nt][0] = ex2((sa[nt][0] - mx0) * k2e);
        sa[nt][1] = ex2((sa[nt][1] - mx0) * k2e);
        sa[nt][2] = ex2((sa[nt][2] - mx1) * k2e);
        sa[nt][3] = ex2((sa[nt][3] - mx1) * k2e);
        s0 += sa[nt][0] + sa[nt][1];
        s1 += sa[nt][2] + sa[nt][3];
    }
    s0 += __shfl_xor_sync(0xffffffffu, s0, 1);
    s0 += __shfl_xor_sync(0xffffffffu, s0, 2);
    s1 += __shfl_xor_sync(0xffffffffu, s1, 1);
    s1 += __shfl_xor_sync(0xffffffffu, s1, 2);
    const float r0v = 1.f / s0, r1v = 1.f / s1;

    cp_wait<0>();                      // V ready
    __syncthreads();                   // V visible to all warps

    float oa[8][4];
    #pragma unroll
    for (int nt = 0; nt < 8; nt++)
        #pragma unroll
        for (int i = 0; i < 4; i++) oa[nt][i] = 0.f;

    // PV: S's C-fragment IS the A-fragment layout — P never touches smem.
    #pragma unroll
    for (int kt = 0; kt < 8; kt++) {
        unsigned a[4];
        a[0] = pack2(sa[2 * kt][0] * r0v,     sa[2 * kt][1] * r0v);
        a[1] = pack2(sa[2 * kt][2] * r1v,     sa[2 * kt][3] * r1v);
        a[2] = pack2(sa[2 * kt + 1][0] * r0v, sa[2 * kt + 1][1] * r0v);
        a[3] = pack2(sa[2 * kt + 1][2] * r1v, sa[2 * kt + 1][3] * r1v);
        #pragma unroll
        for (int p = 0; p < 4; p++) {
            unsigned bb[4];
            ldsm4t(bb, sptr(Vs + (kt * 16 + vro) * 72 + p * 16 + vco));
            mma16(oa[p * 2],     a, bb[0], bb[1]);
            mma16(oa[p * 2 + 1], a, bb[2], bb[3]);
        }
    }

    unsigned short* ob = g_o + (size_t)s * 128 * NC + head * 64;
    #pragma unroll
    for (int nt = 0; nt < 8; nt++) {
        int d0 = nt * 8 + 2 * q;
        *(unsigned*)(ob + (size_t)(m0 + g) * NC + d0)     = pack2(oa[nt][0], oa[nt][1]);
        *(unsigned*)(ob + (size_t)(m0 + g + 8) * NC + d0) = pack2(oa[nt][2], oa[nt][3]);
    }
}

// ---------- output projection (R12): per (t,b,wh) CTA over 64 w, 2 CTAs/SM
// Warp = 32 c x 64 w (2 mt x 8 nt).
__global__ void __launch_bounds__(256, 2) k_proj(const float* __restrict__ bproj,
                                                 float* __restrict__ out) {
    extern __shared__ unsigned shm[];
    unsigned short* Os = (unsigned short*)shm;    // [64 w][264] halves
    const int t = blockIdx.x, b = blockIdx.y, wh = blockIdx.z;
    const int tid = threadIdx.x, lane = tid & 31, wid = tid >> 5;
    const int g = lane >> 2, q = lane & 3;
    const int wm = wid;
    const int kro = (lane & 7) + ((lane >> 4) << 3);
    const int kco = (((lane >> 3) & 1) << 3);

    #pragma unroll
    for (int p = 0; p < 8; p++) {
        int l = tid + p * 256;
        int w = l >> 5, seg = l & 31;
        cp16(sptr(Os + w * 264 + seg * 8),
             g_o + ((size_t)((b * 128 + wh * 64 + w) * 128 + t)) * NC + seg * 8);
    }
    cp_commit();

    float acc[2][8][4];
    #pragma unroll
    for (int mt = 0; mt < 2; mt++)
        #pragma unroll
        for (int nt = 0; nt < 8; nt++)
            #pragma unroll
            for (int i = 0; i < 4; i++) acc[mt][nt][i] = 0.f;

    cp_wait<0>();
    __syncthreads();

    #pragma unroll 4
    for (int kt = 0; kt < 16; kt++) {
        uint4 af[2];
        #pragma unroll
        for (int mt = 0; mt < 2; mt++)
            af[mt] = g_wprojP[((wm * 2 + mt) * 16 + kt) * 32 + lane];
        #pragma unroll
        for (int p = 0; p < 4; p++) {
            unsigned bb[4];
            ldsm4(bb, sptr(Os + (p * 16 + kro) * 264 + kt * 16 + kco));
            #pragma unroll
            for (int mt = 0; mt < 2; mt++) {
                mma16(acc[mt][p * 2],     (const unsigned*)&af[mt], bb[0], bb[1]);
                mma16(acc[mt][p * 2 + 1], (const unsigned*)&af[mt], bb[2], bb[3]);
            }
        }
    }

    #pragma unroll
    for (int mt = 0; mt < 2; mt++) {
        int c0 = wm * 32 + mt * 16 + g;
        float bi0 = bproj[c0], bi1 = bproj[c0 + 8];
        #pragma unroll
        for (int nt = 0; nt < 8; nt++) {
            int w0 = wh * 64 + nt * 8 + 2 * q;
            float2 v0 = { acc[mt][nt][0] + bi0, acc[mt][nt][1] + bi0 };
            float2 v1 = { acc[mt][nt][2] + bi1, acc[mt][nt][3] + bi1 };
            *(float2*)(out + ((size_t)(b * NC + c0) * 128 + t) * 128 + w0) = v0;
            *(float2*)(out + ((size_t)(b * NC + c0 + 8) * 128 + t) * 128 + w0) = v1;
        }
    }
}

extern "C" void kernel_launch(void* const* d_in, const int* in_sizes, int n_in,
                              void* d_out, int out_size) {
    const float* x     = (const float*)d_in[0];
    const float* Wqkv  = (const float*)d_in[1];
    const float* bqkv  = (const float*)d_in[2];
    const float* Wproj = (const float*)d_in[3];
    const float* bproj = (const float*)d_in[4];
    float* out = (float*)d_out;

    cudaFuncSetAttribute(k_qkv,  cudaFuncAttributeMaxDynamicSharedMemorySize, 70656);
    cudaFuncSetAttribute(k_attn, cudaFuncAttributeMaxDynamicSharedMemorySize, 55296);
    cudaFuncSetAttribute(k_proj, cudaFuncAttributeMaxDynamicSharedMemorySize, 33792);

    k_prep<<<128, 256>>>(Wqkv, Wproj);
    k_qkv<<<dim3(128, 8, 2), 256, 70656>>>(x, bqkv);
    k_attn<<<dim3(4, 1024), 256, 55296>>>();
    k_proj<<<dim3(128, 8, 2), 256, 33792>>>(bproj, out);
}